// round 8
// baseline (speedup 1.0000x reference)
#include <cuda_runtime.h>
#include <cstdint>

#define S_TOT 32768
#define CH    16
#define NCHUNK (S_TOT / CH)

// ---------------- static device scratch (16B-aligned: float4 access) ----------------
__device__ __align__(16) float g_fc1[65536u * 128u];
__device__ __align__(16) float g_xg0[2u * 32768u * 512u];
__device__ __align__(16) float g_xg1[2u * 32768u * 512u];
__device__ __align__(16) float g_h0 [2u * 32768u * 128u];
__device__ __align__(16) float g_y  [2u * 256u * 128u];
__device__ int g_prog[8];   // [0..1]: L0 chunk flag per seq; [2+seq*2+half]: producer flags

// ---------------- helpers ----------------
__device__ __forceinline__ int ld_acq(const int* p) {
    int v;
    asm volatile("ld.acquire.gpu.b32 %0, [%1];" : "=r"(v) : "l"(p) : "memory");
    return v;
}
__device__ __forceinline__ void st_rel(int* p, int v) {
    asm volatile("st.release.gpu.b32 [%0], %1;" :: "l"(p), "r"(v) : "memory");
}
__device__ __forceinline__ uint32_t s2u(const void* p) {
    return (uint32_t)__cvta_generic_to_shared(p);
}
__device__ __forceinline__ uint32_t mapa_u32(uint32_t la, uint32_t r) {
    uint32_t ra;
    asm("mapa.shared::cluster.u32 %0, %1, %2;" : "=r"(ra) : "r"(la), "r"(r));
    return ra;
}
__device__ __forceinline__ void st_cluster_f32(uint32_t a, float v) {
    asm volatile("st.shared::cluster.f32 [%0], %1;" :: "r"(a), "f"(v) : "memory");
}
__device__ __forceinline__ void mbar_init(uint32_t mb, uint32_t cnt) {
    asm volatile("mbarrier.init.shared.b64 [%0], %1;" :: "r"(mb), "r"(cnt) : "memory");
}
__device__ __forceinline__ void mbar_arrive_rel_cluster(uint32_t mb) {
    asm volatile("mbarrier.arrive.release.cluster.shared::cluster.b64 _, [%0];"
                 :: "r"(mb) : "memory");
}
__device__ __forceinline__ void mbar_wait(uint32_t mb, uint32_t par) {
    asm volatile(
        "{\n\t.reg .pred P;\n\t"
        "WL%=:\n\t"
        "mbarrier.try_wait.parity.acquire.cluster.shared::cta.b64 P, [%0], %1, 0x989680;\n\t"
        "@P bra.uni WD%=;\n\t"
        "bra.uni WL%=;\n\t"
        "WD%=:\n\t}"
        :: "r"(mb), "r"(par) : "memory");
}
__device__ __forceinline__ void cluster_sync() {
    asm volatile("barrier.cluster.arrive.aligned;" ::: "memory");
    asm volatile("barrier.cluster.wait.aligned;" ::: "memory");
}
__device__ __forceinline__ float tanhap(float x) {
    float r;
    asm("tanh.approx.f32 %0, %1;" : "=f"(r) : "f"(x));
    return r;
}
__device__ __forceinline__ float sigap(float x) {
    return fmaf(0.5f, tanhap(0.5f * x), 0.5f);
}
__device__ __forceinline__ void fma2(uint64_t& acc, uint64_t a, uint64_t b) {
    asm("fma.rn.f32x2 %0, %1, %2, %0;" : "+l"(acc) : "l"(a), "l"(b));
}
__device__ __forceinline__ uint64_t pkf2(float lo, float hi) {
    uint64_t r;
    asm("mov.b64 %0, {%1, %2};" : "=l"(r) : "r"(__float_as_uint(lo)), "r"(__float_as_uint(hi)));
    return r;
}
__device__ __forceinline__ float sum2(uint64_t a) {
    unsigned lo, hi;
    asm("mov.b64 {%0, %1}, %2;" : "=r"(lo), "=r"(hi) : "l"(a));
    return __uint_as_float(lo) + __uint_as_float(hi);
}

// ---------------- init ----------------
__global__ void init_kernel() {
    if (threadIdx.x < 8) g_prog[threadIdx.x] = 0;
}

// ---------------- fc1 = relu(x @ Wfc^T + b) ----------------
__global__ void __launch_bounds__(256) fc1_kernel(const float* __restrict__ inp1,
                                                  const float* __restrict__ inp2,
                                                  const float* __restrict__ Wfc,
                                                  const float* __restrict__ bfc) {
    __shared__ __align__(16) float Ws[128][65];
    __shared__ __align__(16) float As[32][64];
    int tid = threadIdx.x;
    for (int i = tid; i < 128 * 64; i += 256) Ws[i >> 6][i & 63] = Wfc[i];
    int r0 = blockIdx.x * 32;
    for (int i = tid; i < 32 * 64; i += 256) {
        int r = r0 + (i >> 6), k = i & 63;
        const float* src = (r < S_TOT) ? (inp1 + (size_t)r * 64)
                                       : (inp2 + (size_t)(r - S_TOT) * 64);
        As[i >> 6][k] = src[k];
    }
    __syncthreads();
    int n = tid & 127, rb = (tid >> 7) * 16;
    float b = bfc[n];
    for (int rr = 0; rr < 16; rr++) {
        float acc = b;
#pragma unroll
        for (int k = 0; k < 64; k++) acc = fmaf(As[rb + rr][k], Ws[n][k], acc);
        g_fc1[(size_t)(r0 + rb + rr) * 128 + n] = fmaxf(acc, 0.f);
    }
}

// ---------------- xg0 = fc1 @ Wih0^T + (bih0+bhh0) ----------------
__global__ void __launch_bounds__(256) xg0_kernel(const float* __restrict__ Wih,
                                                  const float* __restrict__ bih,
                                                  const float* __restrict__ bhh) {
    __shared__ __align__(16) float As[64][68];
    __shared__ __align__(16) float Bs[64][68];
    int m0 = blockIdx.x * 64, n0 = blockIdx.y * 64;
    int tid = threadIdx.x;
    int tx = tid & 15, ty = tid >> 4;
    float acc[4][4] = {};
    for (int kt = 0; kt < 128; kt += 64) {
        for (int i = tid; i < 64 * 16; i += 256) {
            int r = i >> 4, c = (i & 15) * 4;
            float4 v = *(const float4*)(g_fc1 + (size_t)(m0 + r) * 128 + kt + c);
            As[c + 0][r] = v.x; As[c + 1][r] = v.y; As[c + 2][r] = v.z; As[c + 3][r] = v.w;
        }
        for (int i = tid; i < 64 * 16; i += 256) {
            int r = i >> 4, c = (i & 15) * 4;
            float4 v = *(const float4*)(Wih + (size_t)(n0 + r) * 128 + kt + c);
            Bs[c + 0][r] = v.x; Bs[c + 1][r] = v.y; Bs[c + 2][r] = v.z; Bs[c + 3][r] = v.w;
        }
        __syncthreads();
#pragma unroll
        for (int k = 0; k < 64; k++) {
            float4 a4 = *(const float4*)&As[k][ty * 4];
            float4 b4 = *(const float4*)&Bs[k][tx * 4];
            float a[4] = {a4.x, a4.y, a4.z, a4.w};
            float bb[4] = {b4.x, b4.y, b4.z, b4.w};
#pragma unroll
            for (int x = 0; x < 4; x++)
#pragma unroll
                for (int y = 0; y < 4; y++) acc[x][y] = fmaf(a[x], bb[y], acc[x][y]);
        }
        __syncthreads();
    }
#pragma unroll
    for (int x = 0; x < 4; x++) {
        int m = m0 + ty * 4 + x;
#pragma unroll
        for (int y = 0; y < 4; y++) {
            int n = n0 + tx * 4 + y;
            g_xg0[(size_t)m * 512 + n] = acc[x][y] + bih[n] + bhh[n];
        }
    }
}

// ---------------- clustered recurrence: 4 CTAs, one gate each ----------------
__device__ void rec4(int q, int layer, int seq, const float* __restrict__ Whh) {
    __shared__ __align__(16) float xgs[CH][128];
    __shared__ __align__(16) float gbuf[2][4][128];
    __shared__ __align__(16) float hsm[2][128];
    __shared__ __align__(8) unsigned long long mbar;

    int tid = threadIdx.x;
    int e = tid >> 2, kq = tid & 3;            // element 0..127, k-quarter

    // exact fp32 weights: gate q, element e, K slice [kq*32, kq*32+32)
    uint64_t w[16];
    {
        const uint64_t* wp = (const uint64_t*)
            (Whh + ((size_t)layer * 512 + q * 128 + e) * 128 + kq * 32);
#pragma unroll
        for (int i = 0; i < 16; i++) w[i] = wp[i];
    }

    uint32_t mb_l = s2u(&mbar);
    uint32_t gb_l = s2u(&gbuf[0][0][0]);
    uint32_t mb_r[4], gb_r[4];
#pragma unroll
    for (int c = 0; c < 4; c++) { mb_r[c] = mapa_u32(mb_l, c); gb_r[c] = mapa_u32(gb_l, c); }

    if (tid == 0) mbar_init(mb_l, 4);
    if (tid < 256) ((float*)hsm)[tid] = 0.f;
    __syncthreads();
    cluster_sync();

    const float* xg_src = (layer ? g_xg1 : g_xg0) + (size_t)seq * S_TOT * 512;
    float* hstream = g_h0 + (size_t)seq * S_TOT * 128;
    float* yout = g_y + (size_t)seq * 256u * 128u;
    const int* pflags = &g_prog[2 + seq * 2];
    int* l0flag = &g_prog[seq];

    float cst = 0.f;
    for (int t = 0; t < S_TOT; t++) {
        int s = t & (CH - 1);
        if (s == 0) {
            int ck = t >> 4;
            if (layer == 1) {
                if (tid < 2) { while (ld_acq(pflags + tid) < ck + 1) {} }
                __syncthreads();
            }
            int ss = tid >> 5, f = tid & 31;
            *(float4*)&xgs[ss][f * 4] =
                *(const float4*)(xg_src + (size_t)(ck * CH + ss) * 512 + q * 128 + f * 4);
            __syncthreads();
        }
        int par = t & 1;
        // 32-MAC dot over this thread's K slice
        const float4* h4 = (const float4*)&hsm[par][kq * 32];
        uint64_t a0 = 0ull, a1 = 0ull;
#pragma unroll
        for (int i = 0; i < 8; i++) {
            float4 hv = h4[i];
            fma2(a0, w[2 * i],     pkf2(hv.x, hv.y));
            fma2(a1, w[2 * i + 1], pkf2(hv.z, hv.w));
        }
        float v = sum2(a0) + sum2(a1);
        v += __shfl_xor_sync(0xffffffffu, v, 1);
        v += __shfl_xor_sync(0xffffffffu, v, 2);
        if (kq == 0) {
            v += xgs[s][e];
            uint32_t off = (uint32_t)(((par * 4 + q) * 128 + e) * 4);
#pragma unroll
            for (int c = 0; c < 4; c++) st_cluster_f32(gb_r[c] + off, v);
        }
        __syncthreads();
        if (tid == 0) {
#pragma unroll
            for (int c = 0; c < 4; c++) mbar_arrive_rel_cluster(mb_r[c]);
        }
        if (tid < 128) {
            mbar_wait(mb_l, (uint32_t)par);
            float gi = sigap(gbuf[par][0][tid]);
            float gf = sigap(gbuf[par][1][tid]);
            float gg = tanhap(gbuf[par][2][tid]);
            float go = sigap(gbuf[par][3][tid]);
            cst = fmaf(gf, cst, gi * gg);
            float h = go * tanhap(cst);
            hsm[par ^ 1][tid] = h;
            if (q == 0) {
                if (layer == 0) hstream[(size_t)t * 128 + tid] = h;
                else if (t >= S_TOT - 256)
                    yout[(size_t)(t - (S_TOT - 256)) * 128 + tid] = h;
            }
        }
        __syncthreads();
        if (layer == 0 && q == 0 && s == CH - 1 && tid == 0) {
            asm volatile("fence.acq_rel.gpu;" ::: "memory");
            st_rel(l0flag, (t >> 4) + 1);
        }
    }
    cluster_sync();
}

// ---------------- xg1 producer: f32x2, 256 rows per CTA ----------------
__device__ void producer4(int seq, int half, const float* __restrict__ Wih,
                          const float* __restrict__ bih, const float* __restrict__ bhh) {
    __shared__ __align__(16) float h0s[CH][128];
    int tid = threadIdx.x;
    int row = half * 256 + (tid >> 1), kq = tid & 1;   // K-halves of 64 MACs
    uint64_t w[32];
    {
        const uint64_t* wp = (const uint64_t*)(Wih + (size_t)(512 + row) * 128 + kq * 64);
#pragma unroll
        for (int i = 0; i < 32; i++) w[i] = wp[i];
    }
    float b = bih[512 + row] + bhh[512 + row];
    const float* h0 = g_h0 + (size_t)seq * S_TOT * 128;
    float* xg1 = g_xg1 + (size_t)seq * S_TOT * 512;
    const int* wflag = &g_prog[seq];
    int* sflag = &g_prog[2 + seq * 2 + half];

    for (int ck = 0; ck < NCHUNK; ck++) {
        if (tid == 0) { while (ld_acq(wflag) < ck + 1) {} }
        __syncthreads();
        {
            int ss = tid >> 5, f = tid & 31;
            *(float4*)&h0s[ss][f * 4] =
                *(const float4*)(h0 + (size_t)(ck * CH + ss) * 128 + f * 4);
        }
        __syncthreads();
#pragma unroll 1
        for (int ss = 0; ss < CH; ss++) {
            const float4* h4 = (const float4*)&h0s[ss][kq * 64];
            uint64_t a0 = 0ull, a1 = 0ull;
#pragma unroll
            for (int i = 0; i < 16; i++) {
                float4 hv = h4[i];
                fma2(a0, w[2 * i],     pkf2(hv.x, hv.y));
                fma2(a1, w[2 * i + 1], pkf2(hv.z, hv.w));
            }
            float v = sum2(a0) + sum2(a1);
            v += __shfl_xor_sync(0xffffffffu, v, 1);
            if (kq == 0) xg1[(size_t)(ck * CH + ss) * 512 + row] = v + b;
        }
        __syncthreads();
        if (tid == 0) {
            asm volatile("fence.acq_rel.gpu;" ::: "memory");
            st_rel(sflag, ck + 1);
        }
    }
}

// ---------------- pipeline: 20 CTAs (16 rec in 4 clusters + 4 producers) ----------------
__global__ void __launch_bounds__(512, 1) __cluster_dims__(4, 1, 1)
pipeline4(const float* __restrict__ Whh, const float* __restrict__ Wih,
          const float* __restrict__ bih, const float* __restrict__ bhh) {
    int b = blockIdx.x;
    if (b < 16) {
        uint32_t rank;
        asm("mov.u32 %0, %%cluster_ctarank;" : "=r"(rank));
        int cid = b >> 2;
        rec4((int)rank, cid & 1, cid >> 1, Whh);
    } else {
        int r = b - 16;
        producer4(r >> 1, r & 1, Wih, bih, bhh);
    }
}

// ---------------- head ----------------
__global__ void __launch_bounds__(256) head_kernel(const float* __restrict__ Wh,
                                                   const float* __restrict__ bh,
                                                   float* __restrict__ out) {
    int r = threadIdx.x;
    const float* y1 = g_y + (size_t)r * 128;
    const float* y2 = g_y + 256u * 128u + (size_t)r * 128;
    float s1 = 0.f, s2 = 0.f;
#pragma unroll 8
    for (int k = 0; k < 128; k++) {
        float d = y1[k] - y2[k];
        float w = Wh[k];
        s1 = fmaf(w, fmaxf(d, 0.f), s1);
        s2 = fmaf(w, fmaxf(-d, 0.f), s2);
    }
    float b = bh[0];
    float p1 = s1 + b, p2 = s2 + b, pd = (s1 - s2) + b;
    float m = fmaxf(p1, fmaxf(p2, pd));
    float e1 = expf(p1 - m), e2 = expf(p2 - m), e3 = expf(pd - m);
    float inv = 1.f / (e1 + e2 + e3);
    out[r * 3 + 0] = e1 * inv;
    out[r * 3 + 1] = e2 * inv;
    out[r * 3 + 2] = e3 * inv;
}

// ---------------- launch ----------------
extern "C" void kernel_launch(void* const* d_in, const int* in_sizes, int n_in,
                              void* d_out, int out_size) {
    const float* inp1  = (const float*)d_in[0];
    const float* inp2  = (const float*)d_in[1];
    const float* Wfc   = (const float*)d_in[2];
    const float* bfc   = (const float*)d_in[3];
    const float* Wih   = (const float*)d_in[4];
    const float* Whh   = (const float*)d_in[5];
    const float* bih   = (const float*)d_in[6];
    const float* bhh   = (const float*)d_in[7];
    const float* Whead = (const float*)d_in[8];
    const float* bhead = (const float*)d_in[9];
    float* out = (float*)d_out;

    init_kernel<<<1, 32>>>();
    fc1_kernel<<<2048, 256>>>(inp1, inp2, Wfc, bfc);
    xg0_kernel<<<dim3(1024, 8), 256>>>(Wih, bih, bhh);
    pipeline4<<<20, 512>>>(Whh, Wih, bih, bhh);
    head_kernel<<<1, 256>>>(Whead, bhead, out);
}

// round 9
// speedup vs baseline: 2.4077x; 2.4077x over previous
#include <cuda_runtime.h>
#include <cstdint>

#define S_TOT 32768
#define CH    16
#define NCHUNK (S_TOT / CH)

// ---------------- static device scratch (16B aligned) ----------------
__device__ __align__(16) float g_fc1[65536u * 128u];
__device__ __align__(16) float g_xg0[2u * 32768u * 512u];
__device__ __align__(16) float g_xg1[2u * 32768u * 512u];
__device__ __align__(16) float g_h0 [2u * 32768u * 128u];
__device__ __align__(16) float g_y  [2u * 256u * 128u];
__device__ __align__(16) unsigned g_wpk[2u * 512u * 64u];  // Whh packed bf16x2 per layer/row
__device__ int g_prog[8];  // [seq]: L0 chunk flag; [2+seq*2+half]: producer flags

// ---------------- helpers ----------------
__device__ __forceinline__ int ld_acq(const int* p) {
    int v;
    asm volatile("ld.acquire.gpu.b32 %0, [%1];" : "=r"(v) : "l"(p) : "memory");
    return v;
}
__device__ __forceinline__ void st_rel(int* p, int v) {
    asm volatile("st.release.gpu.b32 [%0], %1;" :: "l"(p), "r"(v) : "memory");
}
__device__ __forceinline__ unsigned bf16rn_bits(float f) {
    unsigned u = __float_as_uint(f);
    return ((u + 0x7fffu + ((u >> 16) & 1u)) >> 16) & 0xffffu;
}
// pack (w_even, w_odd): low16 = bf16(w_even) (recover via <<16); whole word as fp32
// best-approximates w_odd (compensated high half) -> zero-instruction odd operand.
__device__ __forceinline__ unsigned pack2(float we, float wo) {
    unsigned lo = bf16rn_bits(we);
    unsigned t  = __float_as_uint(wo) & 0xffff0000u;
    unsigned best = t | lo;
    float bd = fabsf(__uint_as_float(best) - wo);
    unsigned c = (t + 0x10000u) | lo;
    { float d = fabsf(__uint_as_float(c) - wo); if (d < bd) { bd = d; best = c; } }
    c = (t - 0x10000u) | lo;
    { float d = fabsf(__uint_as_float(c) - wo); if (d < bd) { bd = d; best = c; } }
    return best;
}
__device__ __forceinline__ float tanhap(float x) {
    float r;
    asm("tanh.approx.f32 %0, %1;" : "=f"(r) : "f"(x));
    return r;
}
__device__ __forceinline__ float sigap(float x) {
    return fmaf(0.5f, tanhap(0.5f * x), 0.5f);
}
__device__ __forceinline__ void fma2(uint64_t& acc, uint64_t a, uint64_t b) {
    asm("fma.rn.f32x2 %0, %1, %2, %0;" : "+l"(acc) : "l"(a), "l"(b));
}
__device__ __forceinline__ uint64_t pkf2(float lo, float hi) {
    uint64_t r;
    asm("mov.b64 %0, {%1, %2};" : "=l"(r) : "r"(__float_as_uint(lo)), "r"(__float_as_uint(hi)));
    return r;
}
__device__ __forceinline__ float sum2(uint64_t a) {
    unsigned lo, hi;
    asm("mov.b64 {%0, %1}, %2;" : "=r"(lo), "=r"(hi) : "l"(a));
    return __uint_as_float(lo) + __uint_as_float(hi);
}

// ---------------- prep: pack Whh rows (both layers), init flags ----------------
__global__ void __launch_bounds__(512) prep_kernel(const float* __restrict__ Whh) {
    int layer = blockIdx.x, j = threadIdx.x;
    const float* row = Whh + ((size_t)layer * 512 + j) * 128;
    unsigned* dst = g_wpk + ((size_t)layer * 512 + j) * 64;
    for (int p = 0; p < 64; p++) dst[p] = pack2(row[2 * p], row[2 * p + 1]);
    if (layer == 0 && j < 8) g_prog[j] = 0;
}

// ---------------- fc1 = relu(x @ Wfc^T + b) ----------------
__global__ void __launch_bounds__(256) fc1_kernel(const float* __restrict__ inp1,
                                                  const float* __restrict__ inp2,
                                                  const float* __restrict__ Wfc,
                                                  const float* __restrict__ bfc) {
    __shared__ __align__(16) float Ws[128][65];
    __shared__ __align__(16) float As[32][64];
    int tid = threadIdx.x;
    for (int i = tid; i < 128 * 64; i += 256) Ws[i >> 6][i & 63] = Wfc[i];
    int r0 = blockIdx.x * 32;
    for (int i = tid; i < 32 * 64; i += 256) {
        int r = r0 + (i >> 6), k = i & 63;
        const float* src = (r < S_TOT) ? (inp1 + (size_t)r * 64)
                                       : (inp2 + (size_t)(r - S_TOT) * 64);
        As[i >> 6][k] = src[k];
    }
    __syncthreads();
    int n = tid & 127, rb = (tid >> 7) * 16;
    float b = bfc[n];
    for (int rr = 0; rr < 16; rr++) {
        float acc = b;
#pragma unroll
        for (int k = 0; k < 64; k++) acc = fmaf(As[rb + rr][k], Ws[n][k], acc);
        g_fc1[(size_t)(r0 + rb + rr) * 128 + n] = fmaxf(acc, 0.f);
    }
}

// ---------------- xg0 = fc1 @ Wih0^T + (bih0+bhh0) ----------------
__global__ void __launch_bounds__(256) xg0_kernel(const float* __restrict__ Wih,
                                                  const float* __restrict__ bih,
                                                  const float* __restrict__ bhh) {
    __shared__ __align__(16) float As[64][68];
    __shared__ __align__(16) float Bs[64][68];
    int m0 = blockIdx.x * 64, n0 = blockIdx.y * 64;
    int tid = threadIdx.x;
    int tx = tid & 15, ty = tid >> 4;
    float acc[4][4] = {};
    for (int kt = 0; kt < 128; kt += 64) {
        for (int i = tid; i < 64 * 16; i += 256) {
            int r = i >> 4, c = (i & 15) * 4;
            float4 v = *(const float4*)(g_fc1 + (size_t)(m0 + r) * 128 + kt + c);
            As[c + 0][r] = v.x; As[c + 1][r] = v.y; As[c + 2][r] = v.z; As[c + 3][r] = v.w;
        }
        for (int i = tid; i < 64 * 16; i += 256) {
            int r = i >> 4, c = (i & 15) * 4;
            float4 v = *(const float4*)(Wih + (size_t)(n0 + r) * 128 + kt + c);
            Bs[c + 0][r] = v.x; Bs[c + 1][r] = v.y; Bs[c + 2][r] = v.z; Bs[c + 3][r] = v.w;
        }
        __syncthreads();
#pragma unroll
        for (int k = 0; k < 64; k++) {
            float4 a4 = *(const float4*)&As[k][ty * 4];
            float4 b4 = *(const float4*)&Bs[k][tx * 4];
            float a[4] = {a4.x, a4.y, a4.z, a4.w};
            float bb[4] = {b4.x, b4.y, b4.z, b4.w};
#pragma unroll
            for (int x = 0; x < 4; x++)
#pragma unroll
                for (int y = 0; y < 4; y++) acc[x][y] = fmaf(a[x], bb[y], acc[x][y]);
        }
        __syncthreads();
    }
#pragma unroll
    for (int x = 0; x < 4; x++) {
        int m = m0 + ty * 4 + x;
#pragma unroll
        for (int y = 0; y < 4; y++) {
            int n = n0 + tx * 4 + y;
            g_xg0[(size_t)m * 512 + n] = acc[x][y] + bih[n] + bhh[n];
        }
    }
}

// ---------------- recurrence: 256 threads, hybrid f32x2+packed, 1 barrier/step ----------------
// Thread tid: element e = tid>>1, parity p = tid&1.
//   p=0: exact row = gate i (row e),     packed row = gate f (row 128+e)
//   p=1: exact row = gate g (row 256+e), packed row = gate o (row 384+e)
__device__ void rec_h(const float* __restrict__ whh_layer,   // [512][128] fp32
                      const unsigned* __restrict__ wpk_layer,
                      const float* __restrict__ xg_src,
                      float* __restrict__ h_stream, float* __restrict__ y_out,
                      const int* wflags, int nwf, int* sflag)
{
    __shared__ __align__(16) float xgs[CH][512];
    __shared__ __align__(16) float hsm[2][128];
    int tid = threadIdx.x;
    int e = tid >> 1, p = tid & 1;
    int rowE = p * 256 + e;
    int rowP = rowE + 128;

    uint64_t we[64];
    {
        const uint64_t* wp_ = (const uint64_t*)(whh_layer + (size_t)rowE * 128);
#pragma unroll
        for (int i = 0; i < 64; i++) we[i] = wp_[i];
    }
    unsigned wp[64];
    {
        const unsigned* ws = wpk_layer + (size_t)rowP * 64;
#pragma unroll
        for (int i = 0; i < 64; i++) wp[i] = ws[i];
    }

    if (tid < 128) hsm[0][tid] = 0.f;
    float c = 0.f;
    __syncthreads();

    for (int t = 0; t < S_TOT; t++) {
        int s = t & (CH - 1);
        if (s == 0) {
            int ck = t >> 4;
            if (nwf) {
                if (tid < nwf) { while (ld_acq(wflags + tid) < ck + 1) {} }
                __syncthreads();
            }
            const float4* src = (const float4*)(xg_src + (size_t)ck * CH * 512);
            float4* dst = (float4*)&xgs[0][0];
#pragma unroll
            for (int q = 0; q < 8; q++) dst[tid + 256 * q] = src[tid + 256 * q];
            __syncthreads();
        }
        int par = t & 1;
        const float4* h4 = (const float4*)&hsm[par][0];
        uint64_t a0 = 0ull, a1 = 0ull;              // exact row (f32x2)
        float b0 = 0.f, b1 = 0.f, b2 = 0.f, b3 = 0.f;  // packed row (FFMA)
#pragma unroll
        for (int q = 0; q < 32; q++) {
            float4 hv = h4[q];
            fma2(a0, we[2 * q],     pkf2(hv.x, hv.y));
            fma2(a1, we[2 * q + 1], pkf2(hv.z, hv.w));
            unsigned w01 = wp[2 * q], w23 = wp[2 * q + 1];
            b0 = fmaf(__uint_as_float(w01 << 16), hv.x, b0);
            b1 = fmaf(__uint_as_float(w01),       hv.y, b1);
            b2 = fmaf(__uint_as_float(w23 << 16), hv.z, b2);
            b3 = fmaf(__uint_as_float(w23),       hv.w, b3);
        }
        float vE = (sum2(a0) + sum2(a1)) + xgs[s][rowE];
        float vP = ((b0 + b1) + (b2 + b3)) + xgs[s][rowP];

        float actE = p ? tanhap(vE) : sigap(vE);   // p0: i   p1: g
        float actP = sigap(vP);                    // p0: f   p1: o
        float xE = __shfl_xor_sync(0xffffffffu, actE, 1);  // p0 receives g
        float xP = __shfl_xor_sync(0xffffffffu, actP, 1);  // p0 receives o
        if (p == 0) {
            c = fmaf(actP, c, actE * xE);          // f*c + i*g
            float h = xP * tanhap(c);              // o * tanh(c)
            hsm[par ^ 1][e] = h;
            if (h_stream) h_stream[(size_t)t * 128 + e] = h;
            if (y_out && t >= S_TOT - 256)
                y_out[(size_t)(t - (S_TOT - 256)) * 128 + e] = h;
        }
        __syncthreads();
        if (sflag && s == CH - 1 && tid == 0) {
            asm volatile("fence.acq_rel.gpu;" ::: "memory");
            st_rel(sflag, (t >> 4) + 1);
        }
    }
}

// ---------------- xg1 producer: 256 threads, 1 row each, full f32x2 ----------------
__device__ void producer(int seq, int half, const float* __restrict__ Wih,
                         const float* __restrict__ bih, const float* __restrict__ bhh) {
    __shared__ __align__(16) float h0s[CH][128];
    int tid = threadIdx.x;
    int row = half * 256 + tid;
    uint64_t w[64];
    {
        const uint64_t* wp_ = (const uint64_t*)(Wih + (size_t)(512 + row) * 128);
#pragma unroll
        for (int i = 0; i < 64; i++) w[i] = wp_[i];
    }
    float b = bih[512 + row] + bhh[512 + row];
    const float* h0 = g_h0 + (size_t)seq * S_TOT * 128;
    float* xg1 = g_xg1 + (size_t)seq * S_TOT * 512;
    const int* wflag = &g_prog[seq];
    int* sflag = &g_prog[2 + seq * 2 + half];

    for (int ck = 0; ck < NCHUNK; ck++) {
        if (tid == 0) { while (ld_acq(wflag) < ck + 1) {} }
        __syncthreads();
        {
            const float4* src = (const float4*)(h0 + (size_t)ck * CH * 128);
            float4* dst = (float4*)&h0s[0][0];
            dst[tid]       = src[tid];
            dst[tid + 256] = src[tid + 256];
        }
        __syncthreads();
#pragma unroll 1
        for (int ss = 0; ss < CH; ss++) {
            const float4* h4 = (const float4*)&h0s[ss][0];
            uint64_t a0 = 0ull, a1 = 0ull;
#pragma unroll
            for (int q = 0; q < 32; q++) {
                float4 hv = h4[q];
                fma2(a0, w[2 * q],     pkf2(hv.x, hv.y));
                fma2(a1, w[2 * q + 1], pkf2(hv.z, hv.w));
            }
            xg1[(size_t)(ck * CH + ss) * 512 + row] = (sum2(a0) + sum2(a1)) + b;
        }
        __syncthreads();
        if (tid == 0) {
            asm volatile("fence.acq_rel.gpu;" ::: "memory");
            st_rel(sflag, ck + 1);
        }
    }
}

// ---------------- pipeline: 8 CTAs = 2 seq x {L0rec, prod0, prod1, L1rec} ----------------
__global__ void __launch_bounds__(256, 1)
pipeline_h(const float* __restrict__ Whh, const float* __restrict__ Wih,
           const float* __restrict__ bih, const float* __restrict__ bhh) {
    int b = blockIdx.x, seq = b >> 2, role = b & 3;
    if (role == 0) {
        rec_h(Whh, g_wpk,
              g_xg0 + (size_t)seq * S_TOT * 512,
              g_h0 + (size_t)seq * S_TOT * 128, nullptr,
              nullptr, 0, &g_prog[seq]);
    } else if (role == 3) {
        rec_h(Whh + 512u * 128u, g_wpk + 512u * 64u,
              g_xg1 + (size_t)seq * S_TOT * 512,
              nullptr, g_y + (size_t)seq * 256u * 128u,
              &g_prog[2 + seq * 2], 2, nullptr);
    } else {
        producer(seq, role - 1, Wih, bih, bhh);
    }
}

// ---------------- head ----------------
__global__ void __launch_bounds__(256) head_kernel(const float* __restrict__ Wh,
                                                   const float* __restrict__ bh,
                                                   float* __restrict__ out) {
    int r = threadIdx.x;
    const float* y1 = g_y + (size_t)r * 128;
    const float* y2 = g_y + 256u * 128u + (size_t)r * 128;
    float s1 = 0.f, s2 = 0.f;
#pragma unroll 8
    for (int k = 0; k < 128; k++) {
        float d = y1[k] - y2[k];
        float w = Wh[k];
        s1 = fmaf(w, fmaxf(d, 0.f), s1);
        s2 = fmaf(w, fmaxf(-d, 0.f), s2);
    }
    float b = bh[0];
    float p1 = s1 + b, p2 = s2 + b, pd = (s1 - s2) + b;
    float m = fmaxf(p1, fmaxf(p2, pd));
    float e1 = expf(p1 - m), e2 = expf(p2 - m), e3 = expf(pd - m);
    float inv = 1.f / (e1 + e2 + e3);
    out[r * 3 + 0] = e1 * inv;
    out[r * 3 + 1] = e2 * inv;
    out[r * 3 + 2] = e3 * inv;
}

// ---------------- launch ----------------
extern "C" void kernel_launch(void* const* d_in, const int* in_sizes, int n_in,
                              void* d_out, int out_size) {
    const float* inp1  = (const float*)d_in[0];
    const float* inp2  = (const float*)d_in[1];
    const float* Wfc   = (const float*)d_in[2];
    const float* bfc   = (const float*)d_in[3];
    const float* Wih   = (const float*)d_in[4];
    const float* Whh   = (const float*)d_in[5];
    const float* bih   = (const float*)d_in[6];
    const float* bhh   = (const float*)d_in[7];
    const float* Whead = (const float*)d_in[8];
    const float* bhead = (const float*)d_in[9];
    float* out = (float*)d_out;

    prep_kernel<<<2, 512>>>(Whh);
    fc1_kernel<<<2048, 256>>>(inp1, inp2, Wfc, bfc);
    xg0_kernel<<<dim3(1024, 8), 256>>>(Wih, bih, bhh);
    pipeline_h<<<8, 256>>>(Whh, Wih, bih, bhh);
    head_kernel<<<1, 256>>>(Whead, bhead, out);
}

// round 10
// speedup vs baseline: 2.4566x; 1.0203x over previous
#include <cuda_runtime.h>
#include <cstdint>

#define S_TOT 32768
#define CH    16
#define NCHUNK (S_TOT / CH)

// ---------------- static device scratch (16B aligned) ----------------
__device__ __align__(16) float g_fc1[65536u * 128u];
__device__ __align__(16) float g_xg0[2u * 32768u * 512u];
__device__ __align__(16) float g_xg1[2u * 32768u * 512u];
__device__ __align__(16) float g_h0 [2u * 32768u * 128u];
__device__ __align__(16) float g_y  [2u * 256u * 128u];
__device__ __align__(16) unsigned g_wpk[2u * 512u * 64u];  // Whh packed bf16x2 per layer/row
__device__ int g_prog[8];  // [seq]: L0 chunk flag; [2+seq*2+half]: producer flags

// ---------------- helpers ----------------
__device__ __forceinline__ int ld_acq(const int* p) {
    int v;
    asm volatile("ld.acquire.gpu.b32 %0, [%1];" : "=r"(v) : "l"(p) : "memory");
    return v;
}
__device__ __forceinline__ void st_rel(int* p, int v) {
    asm volatile("st.release.gpu.b32 [%0], %1;" :: "l"(p), "r"(v) : "memory");
}
__device__ __forceinline__ unsigned bf16rn_bits(float f) {
    unsigned u = __float_as_uint(f);
    return ((u + 0x7fffu + ((u >> 16) & 1u)) >> 16) & 0xffffu;
}
// pack (w_even, w_odd): low16 = bf16(w_even) (recover via <<16); whole word as fp32
// best-approximates w_odd (compensated high half) -> zero-instruction odd operand.
__device__ __forceinline__ unsigned pack2(float we, float wo) {
    unsigned lo = bf16rn_bits(we);
    unsigned t  = __float_as_uint(wo) & 0xffff0000u;
    unsigned best = t | lo;
    float bd = fabsf(__uint_as_float(best) - wo);
    unsigned c = (t + 0x10000u) | lo;
    { float d = fabsf(__uint_as_float(c) - wo); if (d < bd) { bd = d; best = c; } }
    c = (t - 0x10000u) | lo;
    { float d = fabsf(__uint_as_float(c) - wo); if (d < bd) { bd = d; best = c; } }
    return best;
}
__device__ __forceinline__ float tanhap(float x) {
    float r;
    asm("tanh.approx.f32 %0, %1;" : "=f"(r) : "f"(x));
    return r;
}
__device__ __forceinline__ float sigap(float x) {
    return fmaf(0.5f, tanhap(0.5f * x), 0.5f);
}
__device__ __forceinline__ void fma2(uint64_t& acc, uint64_t a, uint64_t b) {
    asm("fma.rn.f32x2 %0, %1, %2, %0;" : "+l"(acc) : "l"(a), "l"(b));
}
__device__ __forceinline__ void unpk(uint64_t v, float& lo, float& hi) {
    asm("mov.b64 {%0, %1}, %2;" : "=f"(lo), "=f"(hi) : "l"(v));
}
__device__ __forceinline__ float sum2(uint64_t a) {
    float lo, hi;
    unpk(a, lo, hi);
    return lo + hi;
}
__device__ __forceinline__ uint64_t pkf2(float lo, float hi) {
    uint64_t r;
    asm("mov.b64 %0, {%1, %2};" : "=l"(r) : "r"(__float_as_uint(lo)), "r"(__float_as_uint(hi)));
    return r;
}

// ---------------- prep: pack Whh rows (both layers), init flags ----------------
__global__ void __launch_bounds__(512) prep_kernel(const float* __restrict__ Whh) {
    int layer = blockIdx.x, j = threadIdx.x;
    const float* row = Whh + ((size_t)layer * 512 + j) * 128;
    unsigned* dst = g_wpk + ((size_t)layer * 512 + j) * 64;
    for (int p = 0; p < 64; p++) dst[p] = pack2(row[2 * p], row[2 * p + 1]);
    if (layer == 0 && j < 8) g_prog[j] = 0;
}

// ---------------- fc1 = relu(x @ Wfc^T + b) ----------------
__global__ void __launch_bounds__(256) fc1_kernel(const float* __restrict__ inp1,
                                                  const float* __restrict__ inp2,
                                                  const float* __restrict__ Wfc,
                                                  const float* __restrict__ bfc) {
    __shared__ __align__(16) float Ws[128][65];
    __shared__ __align__(16) float As[32][64];
    int tid = threadIdx.x;
    for (int i = tid; i < 128 * 64; i += 256) Ws[i >> 6][i & 63] = Wfc[i];
    int r0 = blockIdx.x * 32;
    for (int i = tid; i < 32 * 64; i += 256) {
        int r = r0 + (i >> 6), k = i & 63;
        const float* src = (r < S_TOT) ? (inp1 + (size_t)r * 64)
                                       : (inp2 + (size_t)(r - S_TOT) * 64);
        As[i >> 6][k] = src[k];
    }
    __syncthreads();
    int n = tid & 127, rb = (tid >> 7) * 16;
    float b = bfc[n];
    for (int rr = 0; rr < 16; rr++) {
        float acc = b;
#pragma unroll
        for (int k = 0; k < 64; k++) acc = fmaf(As[rb + rr][k], Ws[n][k], acc);
        g_fc1[(size_t)(r0 + rb + rr) * 128 + n] = fmaxf(acc, 0.f);
    }
}

// ---------------- xg0 = fc1 @ Wih0^T + (bih0+bhh0) ----------------
__global__ void __launch_bounds__(256) xg0_kernel(const float* __restrict__ Wih,
                                                  const float* __restrict__ bih,
                                                  const float* __restrict__ bhh) {
    __shared__ __align__(16) float As[64][68];
    __shared__ __align__(16) float Bs[64][68];
    int m0 = blockIdx.x * 64, n0 = blockIdx.y * 64;
    int tid = threadIdx.x;
    int tx = tid & 15, ty = tid >> 4;
    float acc[4][4] = {};
    for (int kt = 0; kt < 128; kt += 64) {
        for (int i = tid; i < 64 * 16; i += 256) {
            int r = i >> 4, c = (i & 15) * 4;
            float4 v = *(const float4*)(g_fc1 + (size_t)(m0 + r) * 128 + kt + c);
            As[c + 0][r] = v.x; As[c + 1][r] = v.y; As[c + 2][r] = v.z; As[c + 3][r] = v.w;
        }
        for (int i = tid; i < 64 * 16; i += 256) {
            int r = i >> 4, c = (i & 15) * 4;
            float4 v = *(const float4*)(Wih + (size_t)(n0 + r) * 128 + kt + c);
            Bs[c + 0][r] = v.x; Bs[c + 1][r] = v.y; Bs[c + 2][r] = v.z; Bs[c + 3][r] = v.w;
        }
        __syncthreads();
#pragma unroll
        for (int k = 0; k < 64; k++) {
            float4 a4 = *(const float4*)&As[k][ty * 4];
            float4 b4 = *(const float4*)&Bs[k][tx * 4];
            float a[4] = {a4.x, a4.y, a4.z, a4.w};
            float bb[4] = {b4.x, b4.y, b4.z, b4.w};
#pragma unroll
            for (int x = 0; x < 4; x++)
#pragma unroll
                for (int y = 0; y < 4; y++) acc[x][y] = fmaf(a[x], bb[y], acc[x][y]);
        }
        __syncthreads();
    }
#pragma unroll
    for (int x = 0; x < 4; x++) {
        int m = m0 + ty * 4 + x;
#pragma unroll
        for (int y = 0; y < 4; y++) {
            int n = n0 + tx * 4 + y;
            g_xg0[(size_t)m * 512 + n] = acc[x][y] + bih[n] + bhh[n];
        }
    }
}

// ---------------- recurrence: 256 threads, hybrid f32x2+packed, 1 barrier/step ----------------
// Thread tid: element e = tid>>1, parity p = tid&1.
//   p=0: exact row = gate i (row e),     packed row = gate f (row 128+e)
//   p=1: exact row = gate g (row 256+e), packed row = gate o (row 384+e)
__device__ void rec_h(const float* __restrict__ whh_layer,   // [512][128] fp32
                      const unsigned* __restrict__ wpk_layer,
                      const float* __restrict__ xg_src,
                      float* __restrict__ h_stream, float* __restrict__ y_out,
                      const int* wflags, int nwf, int* sflag)
{
    __shared__ __align__(16) float xgs[CH][512];
    __shared__ __align__(16) float hsm[2][128];
    int tid = threadIdx.x;
    int e = tid >> 1, p = tid & 1;
    int rowE = p * 256 + e;
    int rowP = rowE + 128;

    uint64_t we[64];
    {
        const uint64_t* wp_ = (const uint64_t*)(whh_layer + (size_t)rowE * 128);
#pragma unroll
        for (int i = 0; i < 64; i++) we[i] = wp_[i];
    }
    unsigned wp[64];
    {
        const unsigned* ws = wpk_layer + (size_t)rowP * 64;
#pragma unroll
        for (int i = 0; i < 64; i++) wp[i] = ws[i];
    }

    if (tid < 128) hsm[0][tid] = 0.f;
    float c = 0.f;
    __syncthreads();

    for (int t = 0; t < S_TOT; t++) {
        int s = t & (CH - 1);
        if (s == 0) {
            int ck = t >> 4;
            if (nwf) {
                if (tid < nwf) { while (ld_acq(wflags + tid) < ck + 1) {} }
                __syncthreads();
            }
            const float4* src = (const float4*)(xg_src + (size_t)ck * CH * 512);
            float4* dst = (float4*)&xgs[0][0];
#pragma unroll
            for (int q = 0; q < 8; q++) dst[tid + 256 * q] = src[tid + 256 * q];
            __syncthreads();
        }
        int par = t & 1;
        const ulonglong2* h2 = (const ulonglong2*)&hsm[par][0];   // 32 x 16B
        uint64_t a0 = 0ull, a1 = 0ull;                 // exact row (f32x2)
        float b0 = 0.f, b1 = 0.f, b2 = 0.f, b3 = 0.f;  // packed row (FFMA)
#pragma unroll
        for (int q = 0; q < 32; q++) {
            ulonglong2 hp = h2[q];                     // h[4q..4q+3] as two f32x2
            fma2(a0, we[2 * q],     hp.x);
            fma2(a1, we[2 * q + 1], hp.y);
            float h0f, h1f, h2f, h3f;
            unpk(hp.x, h0f, h1f);
            unpk(hp.y, h2f, h3f);
            unsigned w01 = wp[2 * q], w23 = wp[2 * q + 1];
            b0 = fmaf(__uint_as_float(w01 << 16), h0f, b0);
            b1 = fmaf(__uint_as_float(w01),       h1f, b1);
            b2 = fmaf(__uint_as_float(w23 << 16), h2f, b2);
            b3 = fmaf(__uint_as_float(w23),       h3f, b3);
        }
        float vE = (sum2(a0) + sum2(a1)) + xgs[s][rowE];
        float vP = ((b0 + b1) + (b2 + b3)) + xgs[s][rowP];

        float actE = p ? tanhap(vE) : sigap(vE);   // p0: i   p1: g
        float actP = sigap(vP);                    // p0: f   p1: o
        float xE = __shfl_xor_sync(0xffffffffu, actE, 1);  // p0 receives g
        float xP = __shfl_xor_sync(0xffffffffu, actP, 1);  // p0 receives o
        if (p == 0) {
            c = fmaf(actP, c, actE * xE);          // f*c + i*g
            float h = xP * tanhap(c);              // o * tanh(c)
            hsm[par ^ 1][e] = h;
            if (h_stream) h_stream[(size_t)t * 128 + e] = h;
            if (y_out && t >= S_TOT - 256)
                y_out[(size_t)(t - (S_TOT - 256)) * 128 + e] = h;
        }
        __syncthreads();
        if (sflag && s == CH - 1 && tid == 0) {
            asm volatile("fence.acq_rel.gpu;" ::: "memory");
            st_rel(sflag, (t >> 4) + 1);
        }
    }
}

// ---------------- xg1 producer: 256 threads, 1 row each, full f32x2 ----------------
__device__ void producer(int seq, int half, const float* __restrict__ Wih,
                         const float* __restrict__ bih, const float* __restrict__ bhh) {
    __shared__ __align__(16) float h0s[CH][128];
    int tid = threadIdx.x;
    int row = half * 256 + tid;
    uint64_t w[64];
    {
        const uint64_t* wp_ = (const uint64_t*)(Wih + (size_t)(512 + row) * 128);
#pragma unroll
        for (int i = 0; i < 64; i++) w[i] = wp_[i];
    }
    float b = bih[512 + row] + bhh[512 + row];
    const float* h0 = g_h0 + (size_t)seq * S_TOT * 128;
    float* xg1 = g_xg1 + (size_t)seq * S_TOT * 512;
    const int* wflag = &g_prog[seq];
    int* sflag = &g_prog[2 + seq * 2 + half];

    for (int ck = 0; ck < NCHUNK; ck++) {
        if (tid == 0) { while (ld_acq(wflag) < ck + 1) {} }
        __syncthreads();
        {
            const float4* src = (const float4*)(h0 + (size_t)ck * CH * 128);
            float4* dst = (float4*)&h0s[0][0];
            dst[tid]       = src[tid];
            dst[tid + 256] = src[tid + 256];
        }
        __syncthreads();
#pragma unroll 1
        for (int ss = 0; ss < CH; ss++) {
            const ulonglong2* h2 = (const ulonglong2*)&h0s[ss][0];
            uint64_t a0 = 0ull, a1 = 0ull;
#pragma unroll
            for (int q = 0; q < 32; q++) {
                ulonglong2 hp = h2[q];
                fma2(a0, w[2 * q],     hp.x);
                fma2(a1, w[2 * q + 1], hp.y);
            }
            xg1[(size_t)(ck * CH + ss) * 512 + row] = (sum2(a0) + sum2(a1)) + b;
        }
        __syncthreads();
        if (tid == 0) {
            asm volatile("fence.acq_rel.gpu;" ::: "memory");
            st_rel(sflag, ck + 1);
        }
    }
}

// ---------------- pipeline: 8 CTAs = 2 seq x {L0rec, prod0, prod1, L1rec} ----------------
__global__ void __launch_bounds__(256, 1)
pipeline_h(const float* __restrict__ Whh, const float* __restrict__ Wih,
           const float* __restrict__ bih, const float* __restrict__ bhh) {
    int b = blockIdx.x, seq = b >> 2, role = b & 3;
    if (role == 0) {
        rec_h(Whh, g_wpk,
              g_xg0 + (size_t)seq * S_TOT * 512,
              g_h0 + (size_t)seq * S_TOT * 128, nullptr,
              nullptr, 0, &g_prog[seq]);
    } else if (role == 3) {
        rec_h(Whh + 512u * 128u, g_wpk + 512u * 64u,
              g_xg1 + (size_t)seq * S_TOT * 512,
              nullptr, g_y + (size_t)seq * 256u * 128u,
              &g_prog[2 + seq * 2], 2, nullptr);
    } else {
        producer(seq, role - 1, Wih, bih, bhh);
    }
}

// ---------------- head ----------------
__global__ void __launch_bounds__(256) head_kernel(const float* __restrict__ Wh,
                                                   const float* __restrict__ bh,
                                                   float* __restrict__ out) {
    int r = threadIdx.x;
    const float* y1 = g_y + (size_t)r * 128;
    const float* y2 = g_y + 256u * 128u + (size_t)r * 128;
    float s1 = 0.f, s2 = 0.f;
#pragma unroll 8
    for (int k = 0; k < 128; k++) {
        float d = y1[k] - y2[k];
        float w = Wh[k];
        s1 = fmaf(w, fmaxf(d, 0.f), s1);
        s2 = fmaf(w, fmaxf(-d, 0.f), s2);
    }
    float b = bh[0];
    float p1 = s1 + b, p2 = s2 + b, pd = (s1 - s2) + b;
    float m = fmaxf(p1, fmaxf(p2, pd));
    float e1 = expf(p1 - m), e2 = expf(p2 - m), e3 = expf(pd - m);
    float inv = 1.f / (e1 + e2 + e3);
    out[r * 3 + 0] = e1 * inv;
    out[r * 3 + 1] = e2 * inv;
    out[r * 3 + 2] = e3 * inv;
}

// ---------------- launch ----------------
extern "C" void kernel_launch(void* const* d_in, const int* in_sizes, int n_in,
                              void* d_out, int out_size) {
    const float* inp1  = (const float*)d_in[0];
    const float* inp2  = (const float*)d_in[1];
    const float* Wfc   = (const float*)d_in[2];
    const float* bfc   = (const float*)d_in[3];
    const float* Wih   = (const float*)d_in[4];
    const float* Whh   = (const float*)d_in[5];
    const float* bih   = (const float*)d_in[6];
    const float* bhh   = (const float*)d_in[7];
    const float* Whead = (const float*)d_in[8];
    const float* bhead = (const float*)d_in[9];
    float* out = (float*)d_out;

    prep_kernel<<<2, 512>>>(Whh);
    fc1_kernel<<<2048, 256>>>(inp1, inp2, Wfc, bfc);
    xg0_kernel<<<dim3(1024, 8), 256>>>(Wih, bih, bhh);
    pipeline_h<<<8, 256>>>(Whh, Wih, bih, bhh);
    head_kernel<<<1, 256>>>(Whead, bhead, out);
}